// round 14
// baseline (speedup 1.0000x reference)
#include <cuda_runtime.h>
#include <cuda_bf16.h>

#define S_IN   44
#define HID    128
#define DD     64
#define VV     16
#define HH     16
#define NRBF   16
#define NEF    16
#define VCIN   17
#define NN     50000
#define NE     800000
#define NLAYER 3

typedef unsigned long long u64;

__device__ float g_s[NN * DD];
__device__ float g_v[NN * VV * 3];
__device__ float g_P[NN * DD];        // per-layer: s@Ws[0:64]+bs
__device__ float g_Vn[NN * 64];       // per-layer: [n][h*4 + {x,y,z,nsq}]
__device__ float g_Mn[NN * 64];       // per-layer: [n][o*4 + {x,y,z,-}]
__device__ float g_aggs[NN * DD];
__device__ float g_aggv[NN * 64];     // padded [node][o:16][4]
__device__ float g_deg[NN];
__device__ float g_invdeg[NN];

__device__ __forceinline__ void red_add_v4(float* p, float a, float b, float c, float d)
{
    asm volatile("red.global.add.v4.f32 [%0], {%1,%2,%3,%4};"
                 :: "l"(p), "f"(a), "f"(b), "f"(c), "f"(d) : "memory");
}
__device__ __forceinline__ u64 pack2(float x, float y)
{
    u64 r; asm("mov.b64 %0, {%1, %2};" : "=l"(r) : "f"(x), "f"(y)); return r;
}
__device__ __forceinline__ void unpack2(u64 v, float& x, float& y)
{
    asm("mov.b64 {%0, %1}, %2;" : "=f"(x), "=f"(y) : "l"(v));
}
__device__ __forceinline__ u64 ffma2(u64 a, u64 b, u64 c)
{
    u64 d; asm("fma.rn.f32x2 %0, %1, %2, %3;" : "=l"(d) : "l"(a), "l"(b), "l"(c)); return d;
}

// ---------------- node embedding ----------------
__global__ __launch_bounds__(128) void embed_kernel(
    const float* __restrict__ sf, const float* __restrict__ W1,
    const float* __restrict__ b1, const float* __restrict__ W2,
    const float* __restrict__ b2, const float* __restrict__ vf)
{
    __shared__ float ssf[8][S_IN];
    __shared__ float sh[8][HID];
    const int nb = blockIdx.x * 8;
    const int t  = threadIdx.x;

    for (int i = t; i < 8 * S_IN; i += 128) {
        int n = i / S_IN, k = i - n * S_IN;
        int node = nb + n;
        ssf[n][k] = (node < NN) ? sf[node * S_IN + k] : 0.f;
    }
    __syncthreads();

    float acc[8];
    float bb = b1[t];
#pragma unroll
    for (int n = 0; n < 8; n++) acc[n] = bb;
    for (int k = 0; k < S_IN; k++) {
        float w = W1[k * HID + t];
#pragma unroll
        for (int n = 0; n < 8; n++) acc[n] += ssf[n][k] * w;
    }
#pragma unroll
    for (int n = 0; n < 8; n++) sh[n][t] = fmaxf(acc[n], 0.f);
    __syncthreads();

    if (t < DD) {
        float acc2[8];
        float b2v = b2[t];
#pragma unroll
        for (int n = 0; n < 8; n++) acc2[n] = b2v;
        for (int k = 0; k < HID; k++) {
            float w = W2[k * DD + t];
#pragma unroll
            for (int n = 0; n < 8; n++) acc2[n] += sh[n][k] * w;
        }
#pragma unroll
        for (int n = 0; n < 8; n++)
            if (nb + n < NN) g_s[(nb + n) * DD + t] = acc2[n];
    }
    for (int i = t; i < 8 * VV * 3; i += 128) {
        int n = i / (VV * 3), k = i - n * (VV * 3);
        int node = nb + n;
        if (node < NN) g_v[node * VV * 3 + k] = vf[node * VV * 3 + k];
    }
}

__global__ void deg_kernel(const int* __restrict__ ei)
{
    int e = blockIdx.x * blockDim.x + threadIdx.x;
    if (e < NE) atomicAdd(&g_deg[ei[NE + e]], 1.0f);
}
__global__ void invdeg_kernel()
{
    int i = blockIdx.x * blockDim.x + threadIdx.x;
    if (i < NN) g_invdeg[i] = 1.0f / fmaxf(g_deg[i], 1.0f);
}

// ---------------- edge kernel: warp = 8 edges, f32x2 GEMV (R10 proven) ----------------
#define EPW 8
#define XI_STR 100
#define SM_STR 68
#define G_STR  20
#define WARP_FLTS 1104
#define OFF_WSV  0                       // 48*64 = 3072
#define OFF_WGT  3072                    // 16*68 = 1088 (Wg^T, stride 68)
#define OFF_BG   4160                    // 16
#define OFF_WH16 4176                    // 16
#define OFF_WMUX 4192                    // 16
#define OFF_SRC  4208                    // 64 ints
#define OFF_DST  4272                    // 64 ints
#define OFF_SCR  4336                    // 16B aligned
#define SMEM_FLOATS (OFF_SCR + 8 * WARP_FLTS)
#define SMEM_BYTES  (SMEM_FLOATS * 4)

__global__ __launch_bounds__(256) void edge_kernel(
    const float* __restrict__ ef, const float* __restrict__ xd,
    const float* __restrict__ dvec, const int* __restrict__ ei,
    const float* __restrict__ Wh, const float* __restrict__ WsV,
    const float* __restrict__ Wmu, const float* __restrict__ Wg,
    const float* __restrict__ bg, int compute_vm)
{
    extern __shared__ float smem[];
    float* sWsV  = smem + OFF_WSV;
    float* sWgT  = smem + OFF_WGT;
    float* sbg   = smem + OFF_BG;
    float* swh16 = smem + OFF_WH16;
    float* swmux = smem + OFF_WMUX;

    const int t = threadIdx.x;
    for (int i = t; i < 48 * 64; i += 256) sWsV[i] = WsV[i];
    for (int i = t; i < 16 * 64; i += 256) {
        int j = i >> 4, o = i & 15;            // Wg[j][o]
        sWgT[o * 68 + j] = Wg[i];
    }
    if (t < 16) {
        sbg[t]   = bg[t];
        swh16[t] = Wh[16 * HH + t];
        float a = 0.f;
#pragma unroll
        for (int h = 0; h < HH; h++) a += Wh[16 * HH + h] * Wmu[h * VV + t];
        swmux[t] = a;
    }
    __syncthreads();

    const int warp = t >> 5, lane = t & 31;
    float* scrXI = smem + OFF_SCR + warp * WARP_FLTS;
    float* scrSM = scrXI + 400;
    float* scrG  = scrXI + 944;
    int* ssrcw = (int*)(smem + OFF_SRC) + warp * EPW;
    int* sdstw = (int*)(smem + OFF_DST) + warp * EPW;

    const int hq  = lane >> 4;                  // half-warp id
    const int h16 = lane & 15;                  // h / o role
    const int q3  = lane >> 2, cg = lane & 3;   // gate roles
    const int qe  = lane >> 2;                  // ef role
    const int j0  = 2 * lane;

    const float inv_sigma = (float)NRBF / 10.0f;
    const float mu_step   = 10.0f / (float)(NRBF - 1);

    const int ntiles = NE / (8 * EPW);          // 12500 exact
    for (int tile = blockIdx.x; tile < ntiles; tile += gridDim.x) {
        const int ebase = tile * (8 * EPW) + warp * EPW;

        // ---- Phase 0/1: coalesced loads + staging ----
        if (lane < 8) {
            ssrcw[lane] = ei[ebase + lane];
            sdstw[lane] = ei[NE + ebase + lane];
        }
        float4 efv = *(const float4*)(ef + (size_t)ebase * 16 + lane * 4);
        float xdv = 0.f, dval = 0.f;
        if (lane < 24) xdv = xd[(size_t)ebase * 3 + lane];
        if (lane < 8)  dval = dvec[ebase + lane];
        __syncwarp();

        {
            float* xip = scrXI + (qe & 3) * XI_STR;
            int jb = (16 + (lane & 3) * 4) * 2 + (qe >> 2);
            xip[jb]     = efv.x;
            xip[jb + 2] = efv.y;
            xip[jb + 4] = efv.z;
            xip[jb + 6] = efv.w;
        }
#pragma unroll
        for (int p = 0; p < 4; p++) {
            int q = 2 * p + hq;
            float de = __shfl_sync(0xffffffffu, dval, q);
            float tt = (de - (float)h16 * mu_step) * inv_sigma;
            scrXI[(q & 3) * XI_STR + h16 * 2 + (q >> 2)] = __expf(-tt * tt);
        }

        // ---- Phase 2: vnorm from hoisted Vn/nsq ----
#pragma unroll
        for (int p = 0; p < 4; p++) {
            int q = 2 * p + hq;
            int sq = ssrcw[q];
            float4 vn = *(const float4*)&g_Vn[(size_t)sq * 64 + h16 * 4];
            float x0 = __shfl_sync(0xffffffffu, xdv, 3 * q);
            float x1 = __shfl_sync(0xffffffffu, xdv, 3 * q + 1);
            float x2 = __shfl_sync(0xffffffffu, xdv, 3 * q + 2);
            float dot = vn.x * x0 + vn.y * x1 + vn.z * x2;
            float xsq = x0 * x0 + x1 * x1 + x2 * x2;
            float w = swh16[h16];
            scrXI[(q & 3) * XI_STR + (32 + h16) * 2 + (q >> 2)] =
                sqrtf(vn.w + 2.f * w * dot + w * w * xsq + 1e-8f);
        }
        __syncwarp();

        // ---- Phase 3: sm = relu(P[src] + X @ WsV), f32x2 over edge pairs ----
        u64 acc0[4], acc1[4];
        {
            float2 pe[8];
#pragma unroll
            for (int q = 0; q < EPW; q++)
                pe[q] = *(const float2*)&g_P[(size_t)ssrcw[q] * 64 + j0];
#pragma unroll
            for (int p = 0; p < 4; p++) {
                acc0[p] = pack2(pe[p].x, pe[p + 4].x);
                acc1[p] = pack2(pe[p].y, pe[p + 4].y);
            }
        }
#pragma unroll
        for (int k = 0; k < 48; k += 2) {
            float2 w0 = *(const float2*)&sWsV[k * DD + j0];
            float2 w1 = *(const float2*)&sWsV[(k + 1) * DD + j0];
            u64 wx0 = pack2(w0.x, w0.x), wy0 = pack2(w0.y, w0.y);
            u64 wx1 = pack2(w1.x, w1.x), wy1 = pack2(w1.y, w1.y);
#pragma unroll
            for (int p = 0; p < 4; p++) {
                ulonglong2 xx = *(const ulonglong2*)(scrXI + p * XI_STR + k * 2);
                acc0[p] = ffma2(xx.x, wx0, acc0[p]);
                acc1[p] = ffma2(xx.x, wy0, acc1[p]);
                acc0[p] = ffma2(xx.y, wx1, acc0[p]);
                acc1[p] = ffma2(xx.y, wy1, acc1[p]);
            }
        }
#pragma unroll
        for (int p = 0; p < 4; p++) {
            float a, b, c, d;
            unpack2(acc0[p], a, b);
            unpack2(acc1[p], c, d);
            *(float2*)&scrSM[p * SM_STR + j0] =
                make_float2(fmaxf(a, 0.f), fmaxf(c, 0.f));
            *(float2*)&scrSM[(p + 4) * SM_STR + j0] =
                make_float2(fmaxf(b, 0.f), fmaxf(d, 0.f));
        }
        __syncwarp();

        // ---- scatter sm (v4) ----
#pragma unroll
        for (int q = 0; q < EPW; q++) {
            if (lane < 16) {
                float4 v = *(const float4*)&scrSM[q * SM_STR + lane * 4];
                red_add_v4(&g_aggs[(size_t)sdstw[q] * 64 + lane * 4],
                           v.x, v.y, v.z, v.w);
            }
        }

        if (compute_vm) {
            // ---- Phase 4: gate ----
            {
                const float* SM = scrSM + q3 * SM_STR;
                float a0 = sbg[cg], a1 = sbg[cg + 4], a2 = sbg[cg + 8], a3 = sbg[cg + 12];
#pragma unroll
                for (int j = 0; j < DD; j += 4) {
                    float4 s4 = *(const float4*)&SM[j];
                    float4 w0 = *(const float4*)&sWgT[cg * 68 + j];
                    float4 w1 = *(const float4*)&sWgT[(cg + 4) * 68 + j];
                    float4 w2 = *(const float4*)&sWgT[(cg + 8) * 68 + j];
                    float4 w3 = *(const float4*)&sWgT[(cg + 12) * 68 + j];
                    a0 += s4.x * w0.x + s4.y * w0.y + s4.z * w0.z + s4.w * w0.w;
                    a1 += s4.x * w1.x + s4.y * w1.y + s4.z * w1.z + s4.w * w1.w;
                    a2 += s4.x * w2.x + s4.y * w2.y + s4.z * w2.z + s4.w * w2.w;
                    a3 += s4.x * w3.x + s4.y * w3.y + s4.z * w3.z + s4.w * w3.w;
                }
                float* G = scrG + q3 * G_STR;
                G[cg]      = 1.f / (1.f + __expf(-a0));
                G[cg + 4]  = 1.f / (1.f + __expf(-a1));
                G[cg + 8]  = 1.f / (1.f + __expf(-a2));
                G[cg + 12] = 1.f / (1.f + __expf(-a3));
            }
            __syncwarp();

            // ---- Phase 5: vm = (Mn[src] + xd*wmux) * gate, direct red.v4 ----
#pragma unroll
            for (int p = 0; p < 4; p++) {
                int q = 2 * p + hq;
                int sq = ssrcw[q], dq = sdstw[q];
                float4 mn = *(const float4*)&g_Mn[(size_t)sq * 64 + h16 * 4];
                float x0 = __shfl_sync(0xffffffffu, xdv, 3 * q);
                float x1 = __shfl_sync(0xffffffffu, xdv, 3 * q + 1);
                float x2 = __shfl_sync(0xffffffffu, xdv, 3 * q + 2);
                float gt = scrG[q * G_STR + h16];
                float wm = swmux[h16];
                red_add_v4(&g_aggv[(size_t)dq * 64 + h16 * 4],
                           (mn.x + x0 * wm) * gt,
                           (mn.y + x1 * wm) * gt,
                           (mn.z + x2 * wm) * gt, 0.f);
            }
        }
        __syncwarp();
    }
}

// ---------------- fused update + per-node precompute (64 nodes / 512 thr, dyn smem) ----------------
// dynamic smem layout (floats):
//  sW  [0, 4096)         sS [4096, 4096+64*65=8256)
//  sv  [8256, 8256+3072=11328)    sVn [11328, 11328+4096=15424)
//  sWh [15424, 15680)    sWm [15680, 15936)
#define UPN 64
#define UP_SW   0
#define UP_SS   4096
#define UP_SV   8256
#define UP_SVN  11328
#define UP_SWH  15424
#define UP_SWM  15680
#define UP_FLOATS 15936
#define UP_SMEM_BYTES (UP_FLOATS * 4)

__global__ __launch_bounds__(512) void update_pre_kernel(
    const float* __restrict__ WsPnext, const float* __restrict__ bsnext,
    const float* __restrict__ Wh, const float* __restrict__ Wmu,
    float* __restrict__ out, int mode, int do_mn)
{
    extern __shared__ float usm[];
    float* sW  = usm + UP_SW;
    float* sS  = usm + UP_SS;
    float* sv  = usm + UP_SV;
    float* sVn = usm + UP_SVN;
    float* sWh = usm + UP_SWH;
    float* sWm = usm + UP_SWM;

    const int t = threadIdx.x;
    const int nb = blockIdx.x * UPN;
    const int nl = t >> 3, j0 = (t & 7) * 8;
    const int node = nb + nl;

    // ---- s path ----
    if (node < NN) {
        float4 s0 = *(const float4*)&g_s[(size_t)node * 64 + j0];
        float4 s1 = *(const float4*)&g_s[(size_t)node * 64 + j0 + 4];
        if (mode != 0) {
            float inv = g_invdeg[node];
            float4 a0 = *(const float4*)&g_aggs[(size_t)node * 64 + j0];
            float4 a1 = *(const float4*)&g_aggs[(size_t)node * 64 + j0 + 4];
            s0.x += a0.x * inv; s0.y += a0.y * inv; s0.z += a0.z * inv; s0.w += a0.w * inv;
            s1.x += a1.x * inv; s1.y += a1.y * inv; s1.z += a1.z * inv; s1.w += a1.w * inv;
            *(float4*)&g_s[(size_t)node * 64 + j0]     = s0;
            *(float4*)&g_s[(size_t)node * 64 + j0 + 4] = s1;
            if (mode == 2) {
                *(float4*)&out[(size_t)node * 64 + j0]     = s0;
                *(float4*)&out[(size_t)node * 64 + j0 + 4] = s1;
            }
        }
        sS[nl * 65 + j0]     = s0.x; sS[nl * 65 + j0 + 1] = s0.y;
        sS[nl * 65 + j0 + 2] = s0.z; sS[nl * 65 + j0 + 3] = s0.w;
        sS[nl * 65 + j0 + 4] = s1.x; sS[nl * 65 + j0 + 5] = s1.y;
        sS[nl * 65 + j0 + 6] = s1.z; sS[nl * 65 + j0 + 7] = s1.w;
    } else {
#pragma unroll
        for (int k = 0; k < 8; k++) sS[nl * 65 + j0 + k] = 0.f;
    }
    if (mode == 2) return;

    // ---- v path ----
    for (int i = t; i < UPN * 48; i += 512) {
        int n2 = i / 48, r = i - n2 * 48;
        int gn = nb + n2;
        float vv = 0.f;
        if (gn < NN) {
            vv = g_v[(size_t)gn * 48 + r];
            if (mode == 1) {
                int o = r / 3, d = r - 3 * o;
                vv += g_aggv[(size_t)gn * 64 + o * 4 + d] * g_invdeg[gn];
                g_v[(size_t)gn * 48 + r] = vv;
            }
        }
        sv[n2 * 48 + r] = vv;
    }

    for (int i = t * 4; i < 64 * 64; i += 2048)
        *(float4*)&sW[i] = *(const float4*)&WsPnext[i];
    if (t < 256) { sWh[t] = Wh[t]; sWm[t] = Wmu[t]; }
    __syncthreads();

    // ---- P GEMM ----
    {
        float4 a0 = *(const float4*)(bsnext + j0);
        float4 a1 = *(const float4*)(bsnext + j0 + 4);
#pragma unroll 8
        for (int k = 0; k < 64; k++) {
            float a = sS[nl * 65 + k];
            float4 w0 = *(const float4*)&sW[k * 64 + j0];
            float4 w1 = *(const float4*)&sW[k * 64 + j0 + 4];
            a0.x += a * w0.x; a0.y += a * w0.y; a0.z += a * w0.z; a0.w += a * w0.w;
            a1.x += a * w1.x; a1.y += a * w1.y; a1.z += a * w1.z; a1.w += a * w1.w;
        }
        if (node < NN) {
            *(float4*)&g_P[(size_t)node * 64 + j0]     = a0;
            *(float4*)&g_P[(size_t)node * 64 + j0 + 4] = a1;
        }
    }

    // ---- Vn = v @ Wh[0:16] ----
    for (int i = t; i < UPN * 48; i += 512) {
        int n = i / 48, r = i - n * 48;
        int h = r / 3, d = r - 3 * h;
        float a = 0.f;
#pragma unroll
        for (int c = 0; c < 16; c++) a += sv[n * 48 + c * 3 + d] * sWh[c * 16 + h];
        sVn[n * 64 + h * 4 + d] = a;
    }
    __syncthreads();

    // ---- nsq + write g_Vn ----
    for (int i = t; i < UPN * 16; i += 512) {
        int n = i >> 4, h = i & 15;
        int gn = nb + n;
        if (gn < NN) {
            float a = sVn[n * 64 + h * 4];
            float b = sVn[n * 64 + h * 4 + 1];
            float c = sVn[n * 64 + h * 4 + 2];
            *(float4*)&g_Vn[(size_t)gn * 64 + h * 4] =
                make_float4(a, b, c, a * a + b * b + c * c);
        }
    }

    // ---- Mn = Vn @ Wmu ----
    if (do_mn) {
        for (int i = t; i < UPN * 48; i += 512) {
            int n = i / 48, r = i - n * 48;
            int o = r / 3, d = r - 3 * o;
            int gn = nb + n;
            if (gn < NN) {
                float a = 0.f;
#pragma unroll
                for (int h = 0; h < 16; h++) a += sVn[n * 64 + h * 4 + d] * sWm[h * 16 + o];
                g_Mn[(size_t)gn * 64 + o * 4 + d] = a;
            }
        }
    }
}

extern "C" void kernel_launch(void* const* d_in, const int* in_sizes, int n_in,
                              void* d_out, int out_size)
{
    const float* sf  = (const float*)d_in[0];
    const float* vf  = (const float*)d_in[2];
    const float* ef  = (const float*)d_in[3];
    const float* xd  = (const float*)d_in[4];
    const float* dv  = (const float*)d_in[5];
    const int*   eix = (const int*)  d_in[6];
    const float* W1  = (const float*)d_in[7];
    const float* b1  = (const float*)d_in[8];
    const float* W2  = (const float*)d_in[9];
    const float* b2  = (const float*)d_in[10];
    const float* Wh  = (const float*)d_in[11];
    const float* Ws  = (const float*)d_in[12];
    const float* bs  = (const float*)d_in[13];
    const float* Wmu = (const float*)d_in[14];
    const float* Wg  = (const float*)d_in[15];
    const float* bg  = (const float*)d_in[16];
    (void)in_sizes; (void)n_in; (void)out_size;

    cudaFuncSetAttribute(edge_kernel,
                         cudaFuncAttributeMaxDynamicSharedMemorySize, SMEM_BYTES);
    cudaFuncSetAttribute(update_pre_kernel,
                         cudaFuncAttributeMaxDynamicSharedMemorySize, UP_SMEM_BYTES);

    void *p_deg = nullptr, *p_aggs = nullptr, *p_aggv = nullptr;
    cudaGetSymbolAddress(&p_deg,  g_deg);
    cudaGetSymbolAddress(&p_aggs, g_aggs);
    cudaGetSymbolAddress(&p_aggv, g_aggv);

    embed_kernel<<<(NN + 7) / 8, 128>>>(sf, W1, b1, W2, b2, vf);
    cudaMemsetAsync(p_deg, 0, NN * sizeof(float));
    deg_kernel<<<(NE + 255) / 256, 256>>>(eix);
    invdeg_kernel<<<(NN + 255) / 256, 256>>>();

    const int nblk = (NN + UPN - 1) / UPN;
    // init: P0, Vn0, Mn0 (layer-0 weights)
    update_pre_kernel<<<nblk, 512, UP_SMEM_BYTES>>>(Ws, bs, Wh, Wmu, nullptr, 0, 1);

    for (int l = 0; l < NLAYER; l++) {
        int vm = (l < NLAYER - 1);
        cudaMemsetAsync(p_aggs, 0, (size_t)NN * 64 * sizeof(float));
        if (vm) cudaMemsetAsync(p_aggv, 0, (size_t)NN * 64 * sizeof(float));
        edge_kernel<<<1184, 256, SMEM_BYTES>>>(
            ef, xd, dv, eix,
            Wh  + l * VCIN * HH,
            Ws  + (size_t)l * 112 * 64 + 64 * 64,
            Wmu + l * HH * VV,
            Wg  + l * DD * VV,
            bg  + l * VV, vm);
        if (l < NLAYER - 1) {
            int ln = l + 1;
            update_pre_kernel<<<nblk, 512, UP_SMEM_BYTES>>>(
                Ws + (size_t)ln * 112 * 64, bs + ln * DD,
                Wh + ln * VCIN * HH, Wmu + ln * HH * VV,
                nullptr, 1, (ln < NLAYER - 1) ? 1 : 0);
        } else {
            update_pre_kernel<<<nblk, 512, UP_SMEM_BYTES>>>(
                Ws, bs, Wh, Wmu, (float*)d_out, 2, 0);
        }
    }
}

// round 15
// speedup vs baseline: 1.0121x; 1.0121x over previous
#include <cuda_runtime.h>
#include <cuda_bf16.h>

#define S_IN   44
#define HID    128
#define DD     64
#define VV     16
#define HH     16
#define NRBF   16
#define NEF    16
#define VCIN   17
#define NN     50000
#define NE     800000
#define NLAYER 3

typedef unsigned long long u64;

__device__ float g_s[NN * DD];
__device__ float g_v[NN * VV * 3];
__device__ float g_P[NN * DD];        // per-layer: s@Ws[0:64]+bs
__device__ float g_Vn[NN * 64];       // per-layer: [n][h*4 + {x,y,z,nsq}]
__device__ float g_Mn[NN * 64];       // per-layer: [n][o*4 + {x,y,z,-}]
__device__ float g_aggs[NN * DD];
__device__ float g_aggv[NN * 64];     // padded [node][o:16][4]
__device__ float g_deg[NN];
__device__ float g_invdeg[NN];

__device__ __forceinline__ void red_add_v4(float* p, float a, float b, float c, float d)
{
    asm volatile("red.global.add.v4.f32 [%0], {%1,%2,%3,%4};"
                 :: "l"(p), "f"(a), "f"(b), "f"(c), "f"(d) : "memory");
}
__device__ __forceinline__ u64 pack2(float x, float y)
{
    u64 r; asm("mov.b64 %0, {%1, %2};" : "=l"(r) : "f"(x), "f"(y)); return r;
}
__device__ __forceinline__ void unpack2(u64 v, float& x, float& y)
{
    asm("mov.b64 {%0, %1}, %2;" : "=f"(x), "=f"(y) : "l"(v));
}
__device__ __forceinline__ u64 ffma2(u64 a, u64 b, u64 c)
{
    u64 d; asm("fma.rn.f32x2 %0, %1, %2, %3;" : "=l"(d) : "l"(a), "l"(b), "l"(c)); return d;
}

// ---------------- node embedding ----------------
__global__ __launch_bounds__(128) void embed_kernel(
    const float* __restrict__ sf, const float* __restrict__ W1,
    const float* __restrict__ b1, const float* __restrict__ W2,
    const float* __restrict__ b2, const float* __restrict__ vf)
{
    __shared__ float ssf[8][S_IN];
    __shared__ float sh[8][HID];
    const int nb = blockIdx.x * 8;
    const int t  = threadIdx.x;

    for (int i = t; i < 8 * S_IN; i += 128) {
        int n = i / S_IN, k = i - n * S_IN;
        int node = nb + n;
        ssf[n][k] = (node < NN) ? sf[node * S_IN + k] : 0.f;
    }
    __syncthreads();

    float acc[8];
    float bb = b1[t];
#pragma unroll
    for (int n = 0; n < 8; n++) acc[n] = bb;
    for (int k = 0; k < S_IN; k++) {
        float w = W1[k * HID + t];
#pragma unroll
        for (int n = 0; n < 8; n++) acc[n] += ssf[n][k] * w;
    }
#pragma unroll
    for (int n = 0; n < 8; n++) sh[n][t] = fmaxf(acc[n], 0.f);
    __syncthreads();

    if (t < DD) {
        float acc2[8];
        float b2v = b2[t];
#pragma unroll
        for (int n = 0; n < 8; n++) acc2[n] = b2v;
        for (int k = 0; k < HID; k++) {
            float w = W2[k * DD + t];
#pragma unroll
            for (int n = 0; n < 8; n++) acc2[n] += sh[n][k] * w;
        }
#pragma unroll
        for (int n = 0; n < 8; n++)
            if (nb + n < NN) g_s[(nb + n) * DD + t] = acc2[n];
    }
    for (int i = t; i < 8 * VV * 3; i += 128) {
        int n = i / (VV * 3), k = i - n * (VV * 3);
        int node = nb + n;
        if (node < NN) g_v[node * VV * 3 + k] = vf[node * VV * 3 + k];
    }
}

__global__ void deg_kernel(const int* __restrict__ ei)
{
    int e = blockIdx.x * blockDim.x + threadIdx.x;
    if (e < NE) atomicAdd(&g_deg[ei[NE + e]], 1.0f);
}
__global__ void invdeg_kernel()
{
    int i = blockIdx.x * blockDim.x + threadIdx.x;
    if (i < NN) g_invdeg[i] = 1.0f / fmaxf(g_deg[i], 1.0f);
}

// ---------------- edge kernel: warp = 8 edges, f32x2 GEMV + tile prefetch ----------------
#define EPW 8
#define XI_STR 100
#define SM_STR 68
#define G_STR  20
#define WARP_FLTS 1104
#define OFF_WSV  0                       // 48*64 = 3072
#define OFF_WGT  3072                    // 16*68 = 1088 (Wg^T, stride 68)
#define OFF_BG   4160                    // 16
#define OFF_WH16 4176                    // 16
#define OFF_WMUX 4192                    // 16
#define OFF_SRC  4208                    // 64 ints
#define OFF_DST  4272                    // 64 ints
#define OFF_SCR  4336                    // 16B aligned
#define SMEM_FLOATS (OFF_SCR + 8 * WARP_FLTS)
#define SMEM_BYTES  (SMEM_FLOATS * 4)

__global__ __launch_bounds__(256) void edge_kernel(
    const float* __restrict__ ef, const float* __restrict__ xd,
    const float* __restrict__ dvec, const int* __restrict__ ei,
    const float* __restrict__ Wh, const float* __restrict__ WsV,
    const float* __restrict__ Wmu, const float* __restrict__ Wg,
    const float* __restrict__ bg, int compute_vm)
{
    extern __shared__ float smem[];
    float* sWsV  = smem + OFF_WSV;
    float* sWgT  = smem + OFF_WGT;
    float* sbg   = smem + OFF_BG;
    float* swh16 = smem + OFF_WH16;
    float* swmux = smem + OFF_WMUX;

    const int t = threadIdx.x;
    for (int i = t; i < 48 * 64; i += 256) sWsV[i] = WsV[i];
    for (int i = t; i < 16 * 64; i += 256) {
        int j = i >> 4, o = i & 15;            // Wg[j][o]
        sWgT[o * 68 + j] = Wg[i];
    }
    if (t < 16) {
        sbg[t]   = bg[t];
        swh16[t] = Wh[16 * HH + t];
        float a = 0.f;
#pragma unroll
        for (int h = 0; h < HH; h++) a += Wh[16 * HH + h] * Wmu[h * VV + t];
        swmux[t] = a;
    }
    __syncthreads();

    const int warp = t >> 5, lane = t & 31;
    float* scrXI = smem + OFF_SCR + warp * WARP_FLTS;
    float* scrSM = scrXI + 400;
    float* scrG  = scrXI + 944;
    int* ssrcw = (int*)(smem + OFF_SRC) + warp * EPW;
    int* sdstw = (int*)(smem + OFF_DST) + warp * EPW;

    const int hq  = lane >> 4;                  // half-warp id
    const int h16 = lane & 15;                  // h / o role
    const int q3  = lane >> 2, cg = lane & 3;   // gate roles
    const int qe  = lane >> 2;                  // ef role
    const int j0  = 2 * lane;

    const float inv_sigma = (float)NRBF / 10.0f;
    const float mu_step   = 10.0f / (float)(NRBF - 1);

    const int ntiles = NE / (8 * EPW);          // 12500 exact

    // ---- prologue: load first tile's coalesced inputs into registers ----
    int tile = blockIdx.x;
    int csrc = 0, cdst = 0;
    float4 cefv = make_float4(0.f, 0.f, 0.f, 0.f);
    float cxdv = 0.f, cdval = 0.f;
    if (tile < ntiles) {
        const int eb = tile * (8 * EPW) + warp * EPW;
        if (lane < 8) { csrc = ei[eb + lane]; cdst = ei[NE + eb + lane]; }
        cefv = *(const float4*)(ef + (size_t)eb * 16 + lane * 4);
        if (lane < 24) cxdv = xd[(size_t)eb * 3 + lane];
        if (lane < 8)  cdval = dvec[eb + lane];
    }

    for (; tile < ntiles; ) {
        const int ntile = tile + gridDim.x;

        // ---- Phase 0/1: stage current tile from registers ----
        if (lane < 8) { ssrcw[lane] = csrc; sdstw[lane] = cdst; }
        __syncwarp();

        {
            float* xip = scrXI + (qe & 3) * XI_STR;
            int jb = (16 + (lane & 3) * 4) * 2 + (qe >> 2);
            xip[jb]     = cefv.x;
            xip[jb + 2] = cefv.y;
            xip[jb + 4] = cefv.z;
            xip[jb + 6] = cefv.w;
        }
#pragma unroll
        for (int p = 0; p < 4; p++) {
            int q = 2 * p + hq;
            float de = __shfl_sync(0xffffffffu, cdval, q);
            float tt = (de - (float)h16 * mu_step) * inv_sigma;
            scrXI[(q & 3) * XI_STR + h16 * 2 + (q >> 2)] = __expf(-tt * tt);
        }

        // ---- Phase 2: vnorm from hoisted Vn/nsq ----
#pragma unroll
        for (int p = 0; p < 4; p++) {
            int q = 2 * p + hq;
            int sq = ssrcw[q];
            float4 vn = *(const float4*)&g_Vn[(size_t)sq * 64 + h16 * 4];
            float x0 = __shfl_sync(0xffffffffu, cxdv, 3 * q);
            float x1 = __shfl_sync(0xffffffffu, cxdv, 3 * q + 1);
            float x2 = __shfl_sync(0xffffffffu, cxdv, 3 * q + 2);
            float dot = vn.x * x0 + vn.y * x1 + vn.z * x2;
            float xsq = x0 * x0 + x1 * x1 + x2 * x2;
            float w = swh16[h16];
            scrXI[(q & 3) * XI_STR + (32 + h16) * 2 + (q >> 2)] =
                sqrtf(vn.w + 2.f * w * dot + w * w * xsq + 1e-8f);
        }
        __syncwarp();

        // ---- Phase 3: sm = relu(P[src] + X @ WsV), f32x2 over edge pairs ----
        u64 acc0[4], acc1[4];
        {
            float2 pe[8];
#pragma unroll
            for (int q = 0; q < EPW; q++)
                pe[q] = *(const float2*)&g_P[(size_t)ssrcw[q] * 64 + j0];
#pragma unroll
            for (int p = 0; p < 4; p++) {
                acc0[p] = pack2(pe[p].x, pe[p + 4].x);
                acc1[p] = pack2(pe[p].y, pe[p + 4].y);
            }
        }
#pragma unroll
        for (int k = 0; k < 48; k += 2) {
            float2 w0 = *(const float2*)&sWsV[k * DD + j0];
            float2 w1 = *(const float2*)&sWsV[(k + 1) * DD + j0];
            u64 wx0 = pack2(w0.x, w0.x), wy0 = pack2(w0.y, w0.y);
            u64 wx1 = pack2(w1.x, w1.x), wy1 = pack2(w1.y, w1.y);
#pragma unroll
            for (int p = 0; p < 4; p++) {
                ulonglong2 xx = *(const ulonglong2*)(scrXI + p * XI_STR + k * 2);
                acc0[p] = ffma2(xx.x, wx0, acc0[p]);
                acc1[p] = ffma2(xx.x, wy0, acc1[p]);
                acc0[p] = ffma2(xx.y, wx1, acc0[p]);
                acc1[p] = ffma2(xx.y, wy1, acc1[p]);
            }
        }
#pragma unroll
        for (int p = 0; p < 4; p++) {
            float a, b, c, d;
            unpack2(acc0[p], a, b);
            unpack2(acc1[p], c, d);
            *(float2*)&scrSM[p * SM_STR + j0] =
                make_float2(fmaxf(a, 0.f), fmaxf(c, 0.f));
            *(float2*)&scrSM[(p + 4) * SM_STR + j0] =
                make_float2(fmaxf(b, 0.f), fmaxf(d, 0.f));
        }
        __syncwarp();

        // ---- scatter sm (v4) ----
#pragma unroll
        for (int q = 0; q < EPW; q++) {
            if (lane < 16) {
                float4 v = *(const float4*)&scrSM[q * SM_STR + lane * 4];
                red_add_v4(&g_aggs[(size_t)sdstw[q] * 64 + lane * 4],
                           v.x, v.y, v.z, v.w);
            }
        }

        // ---- PREFETCH next tile's coalesced inputs (overlaps gate/phase 5) ----
        int nsrc = 0, ndst = 0;
        float4 nefv = make_float4(0.f, 0.f, 0.f, 0.f);
        float nxdv = 0.f, ndval = 0.f;
        if (ntile < ntiles) {
            const int neb = ntile * (8 * EPW) + warp * EPW;
            if (lane < 8) { nsrc = ei[neb + lane]; ndst = ei[NE + neb + lane]; }
            nefv = *(const float4*)(ef + (size_t)neb * 16 + lane * 4);
            if (lane < 24) nxdv = xd[(size_t)neb * 3 + lane];
            if (lane < 8)  ndval = dvec[neb + lane];
        }

        if (compute_vm) {
            // ---- Phase 4: gate ----
            {
                const float* SM = scrSM + q3 * SM_STR;
                float a0 = sbg[cg], a1 = sbg[cg + 4], a2 = sbg[cg + 8], a3 = sbg[cg + 12];
#pragma unroll
                for (int j = 0; j < DD; j += 4) {
                    float4 s4 = *(const float4*)&SM[j];
                    float4 w0 = *(const float4*)&sWgT[cg * 68 + j];
                    float4 w1 = *(const float4*)&sWgT[(cg + 4) * 68 + j];
                    float4 w2 = *(const float4*)&sWgT[(cg + 8) * 68 + j];
                    float4 w3 = *(const float4*)&sWgT[(cg + 12) * 68 + j];
                    a0 += s4.x * w0.x + s4.y * w0.y + s4.z * w0.z + s4.w * w0.w;
                    a1 += s4.x * w1.x + s4.y * w1.y + s4.z * w1.z + s4.w * w1.w;
                    a2 += s4.x * w2.x + s4.y * w2.y + s4.z * w2.z + s4.w * w2.w;
                    a3 += s4.x * w3.x + s4.y * w3.y + s4.z * w3.z + s4.w * w3.w;
                }
                float* G = scrG + q3 * G_STR;
                G[cg]      = 1.f / (1.f + __expf(-a0));
                G[cg + 4]  = 1.f / (1.f + __expf(-a1));
                G[cg + 8]  = 1.f / (1.f + __expf(-a2));
                G[cg + 12] = 1.f / (1.f + __expf(-a3));
            }
            __syncwarp();

            // ---- Phase 5: vm = (Mn[src] + xd*wmux) * gate, direct red.v4 ----
#pragma unroll
            for (int p = 0; p < 4; p++) {
                int q = 2 * p + hq;
                int sq = ssrcw[q], dq = sdstw[q];
                float4 mn = *(const float4*)&g_Mn[(size_t)sq * 64 + h16 * 4];
                float x0 = __shfl_sync(0xffffffffu, cxdv, 3 * q);
                float x1 = __shfl_sync(0xffffffffu, cxdv, 3 * q + 1);
                float x2 = __shfl_sync(0xffffffffu, cxdv, 3 * q + 2);
                float gt = scrG[q * G_STR + h16];
                float wm = swmux[h16];
                red_add_v4(&g_aggv[(size_t)dq * 64 + h16 * 4],
                           (mn.x + x0 * wm) * gt,
                           (mn.y + x1 * wm) * gt,
                           (mn.z + x2 * wm) * gt, 0.f);
            }
        }
        __syncwarp();

        // ---- rotate prefetched registers ----
        csrc = nsrc; cdst = ndst; cefv = nefv; cxdv = nxdv; cdval = ndval;
        tile = ntile;
    }
}

// ---------------- fused update + per-node precompute (32 nodes / 256 thr) ----------------
// mode: 0 = init, 1 = mid (update s,v), 2 = last (s only + out)
__global__ __launch_bounds__(256) void update_pre_kernel(
    const float* __restrict__ WsPnext, const float* __restrict__ bsnext,
    const float* __restrict__ Wh, const float* __restrict__ Wmu,
    float* __restrict__ out, int mode, int do_mn)
{
    __shared__ float sW[64 * 64];
    __shared__ float sS[32 * 65];
    __shared__ float sv[32 * 48];
    __shared__ float sVn[32 * 64];
    __shared__ float sWh[16 * 16];
    __shared__ float sWm[16 * 16];

    const int t = threadIdx.x;
    const int nb = blockIdx.x * 32;
    const int nl = t >> 3, j0 = (t & 7) * 8;
    const int node = nb + nl;

    // ---- s path ----
    if (node < NN) {
        float4 s0 = *(const float4*)&g_s[(size_t)node * 64 + j0];
        float4 s1 = *(const float4*)&g_s[(size_t)node * 64 + j0 + 4];
        if (mode != 0) {
            float inv = g_invdeg[node];
            float4 a0 = *(const float4*)&g_aggs[(size_t)node * 64 + j0];
            float4 a1 = *(const float4*)&g_aggs[(size_t)node * 64 + j0 + 4];
            s0.x += a0.x * inv; s0.y += a0.y * inv; s0.z += a0.z * inv; s0.w += a0.w * inv;
            s1.x += a1.x * inv; s1.y += a1.y * inv; s1.z += a1.z * inv; s1.w += a1.w * inv;
            *(float4*)&g_s[(size_t)node * 64 + j0]     = s0;
            *(float4*)&g_s[(size_t)node * 64 + j0 + 4] = s1;
            if (mode == 2) {
                *(float4*)&out[(size_t)node * 64 + j0]     = s0;
                *(float4*)&out[(size_t)node * 64 + j0 + 4] = s1;
            }
        }
        sS[nl * 65 + j0]     = s0.x; sS[nl * 65 + j0 + 1] = s0.y;
        sS[nl * 65 + j0 + 2] = s0.z; sS[nl * 65 + j0 + 3] = s0.w;
        sS[nl * 65 + j0 + 4] = s1.x; sS[nl * 65 + j0 + 5] = s1.y;
        sS[nl * 65 + j0 + 6] = s1.z; sS[nl * 65 + j0 + 7] = s1.w;
    } else {
#pragma unroll
        for (int k = 0; k < 8; k++) sS[nl * 65 + j0 + k] = 0.f;
    }
    if (mode == 2) return;

    // ---- v path ----
    for (int i = t; i < 32 * 48; i += 256) {
        int n2 = i / 48, r = i - n2 * 48;
        int gn = nb + n2;
        float vv = 0.f;
        if (gn < NN) {
            vv = g_v[(size_t)gn * 48 + r];
            if (mode == 1) {
                int o = r / 3, d = r - 3 * o;
                vv += g_aggv[(size_t)gn * 64 + o * 4 + d] * g_invdeg[gn];
                g_v[(size_t)gn * 48 + r] = vv;
            }
        }
        sv[n2 * 48 + r] = vv;
    }

    for (int i = t * 4; i < 64 * 64; i += 1024)
        *(float4*)&sW[i] = *(const float4*)&WsPnext[i];
    if (t < 256) { sWh[t] = Wh[t]; sWm[t] = Wmu[t]; }
    __syncthreads();

    // ---- P GEMM ----
    {
        float4 a0 = *(const float4*)(bsnext + j0);
        float4 a1 = *(const float4*)(bsnext + j0 + 4);
#pragma unroll 8
        for (int k = 0; k < 64; k++) {
            float a = sS[nl * 65 + k];
            float4 w0 = *(const float4*)&sW[k * 64 + j0];
            float4 w1 = *(const float4*)&sW[k * 64 + j0 + 4];
            a0.x += a * w0.x; a0.y += a * w0.y; a0.z += a * w0.z; a0.w += a * w0.w;
            a1.x += a * w1.x; a1.y += a * w1.y; a1.z += a * w1.z; a1.w += a * w1.w;
        }
        if (node < NN) {
            *(float4*)&g_P[(size_t)node * 64 + j0]     = a0;
            *(float4*)&g_P[(size_t)node * 64 + j0 + 4] = a1;
        }
    }

    // ---- Vn = v @ Wh[0:16] ----
    for (int i = t; i < 32 * 48; i += 256) {
        int n = i / 48, r = i - n * 48;
        int h = r / 3, d = r - 3 * h;
        float a = 0.f;
#pragma unroll
        for (int c = 0; c < 16; c++) a += sv[n * 48 + c * 3 + d] * sWh[c * 16 + h];
        sVn[n * 64 + h * 4 + d] = a;
    }
    __syncthreads();

    // ---- nsq + write g_Vn ----
    for (int i = t; i < 32 * 16; i += 256) {
        int n = i >> 4, h = i & 15;
        int gn = nb + n;
        if (gn < NN) {
            float a = sVn[n * 64 + h * 4];
            float b = sVn[n * 64 + h * 4 + 1];
            float c = sVn[n * 64 + h * 4 + 2];
            *(float4*)&g_Vn[(size_t)gn * 64 + h * 4] =
                make_float4(a, b, c, a * a + b * b + c * c);
        }
    }

    // ---- Mn = Vn @ Wmu ----
    if (do_mn) {
        for (int i = t; i < 32 * 48; i += 256) {
            int n = i / 48, r = i - n * 48;
            int o = r / 3, d = r - 3 * o;
            int gn = nb + n;
            if (gn < NN) {
                float a = 0.f;
#pragma unroll
                for (int h = 0; h < 16; h++) a += sVn[n * 64 + h * 4 + d] * sWm[h * 16 + o];
                g_Mn[(size_t)gn * 64 + o * 4 + d] = a;
            }
        }
    }
}

extern "C" void kernel_launch(void* const* d_in, const int* in_sizes, int n_in,
                              void* d_out, int out_size)
{
    const float* sf  = (const float*)d_in[0];
    const float* vf  = (const float*)d_in[2];
    const float* ef  = (const float*)d_in[3];
    const float* xd  = (const float*)d_in[4];
    const float* dv  = (const float*)d_in[5];
    const int*   eix = (const int*)  d_in[6];
    const float* W1  = (const float*)d_in[7];
    const float* b1  = (const float*)d_in[8];
    const float* W2  = (const float*)d_in[9];
    const float* b2  = (const float*)d_in[10];
    const float* Wh  = (const float*)d_in[11];
    const float* Ws  = (const float*)d_in[12];
    const float* bs  = (const float*)d_in[13];
    const float* Wmu = (const float*)d_in[14];
    const float* Wg  = (const float*)d_in[15];
    const float* bg  = (const float*)d_in[16];
    (void)in_sizes; (void)n_in; (void)out_size;

    cudaFuncSetAttribute(edge_kernel,
                         cudaFuncAttributeMaxDynamicSharedMemorySize, SMEM_BYTES);

    void *p_deg = nullptr, *p_aggs = nullptr, *p_aggv = nullptr;
    cudaGetSymbolAddress(&p_deg,  g_deg);
    cudaGetSymbolAddress(&p_aggs, g_aggs);
    cudaGetSymbolAddress(&p_aggv, g_aggv);

    embed_kernel<<<(NN + 7) / 8, 128>>>(sf, W1, b1, W2, b2, vf);
    cudaMemsetAsync(p_deg, 0, NN * sizeof(float));
    deg_kernel<<<(NE + 255) / 256, 256>>>(eix);
    invdeg_kernel<<<(NN + 255) / 256, 256>>>();

    const int nblk = (NN + 31) / 32;
    // init: P0, Vn0, Mn0 (layer-0 weights)
    update_pre_kernel<<<nblk, 256>>>(Ws, bs, Wh, Wmu, nullptr, 0, 1);

    for (int l = 0; l < NLAYER; l++) {
        int vm = (l < NLAYER - 1);
        cudaMemsetAsync(p_aggs, 0, (size_t)NN * 64 * sizeof(float));
        if (vm) cudaMemsetAsync(p_aggv, 0, (size_t)NN * 64 * sizeof(float));
        edge_kernel<<<1184, 256, SMEM_BYTES>>>(
            ef, xd, dv, eix,
            Wh  + l * VCIN * HH,
            Ws  + (size_t)l * 112 * 64 + 64 * 64,
            Wmu + l * HH * VV,
            Wg  + l * DD * VV,
            bg  + l * VV, vm);
        if (l < NLAYER - 1) {
            int ln = l + 1;
            update_pre_kernel<<<nblk, 256>>>(
                Ws + (size_t)ln * 112 * 64, bs + ln * DD,
                Wh + ln * VCIN * HH, Wmu + ln * HH * VV,
                nullptr, 1, (ln < NLAYER - 1) ? 1 : 0);
        } else {
            update_pre_kernel<<<nblk, 256>>>(
                Ws, bs, Wh, Wmu, (float*)d_out, 2, 0);
        }
    }
}

// round 16
// speedup vs baseline: 1.0195x; 1.0073x over previous
#include <cuda_runtime.h>
#include <cuda_bf16.h>

#define S_IN   44
#define HID    128
#define DD     64
#define VV     16
#define HH     16
#define NRBF   16
#define NEF    16
#define VCIN   17
#define NN     50000
#define NE     800000
#define NLAYER 3

typedef unsigned long long u64;

__device__ float g_s[NN * DD];
__device__ float g_v[NN * VV * 3];
__device__ float g_P[NN * DD];        // per-layer: s@Ws[0:64]+bs
__device__ float g_Vn[NN * 64];       // per-layer: [n][h*4 + {x,y,z,nsq}]
__device__ float g_Mn[NN * 64];       // per-layer: [n][o*4 + {x,y,z,-}]
__device__ float g_aggs[NN * DD];
__device__ float g_aggv[NN * 64];     // padded [node][o:16][4]
__device__ float g_deg[NN];
__device__ float g_invdeg[NN];

__device__ __forceinline__ void red_add_v4(float* p, float a, float b, float c, float d)
{
    asm volatile("red.global.add.v4.f32 [%0], {%1,%2,%3,%4};"
                 :: "l"(p), "f"(a), "f"(b), "f"(c), "f"(d) : "memory");
}
__device__ __forceinline__ u64 pack2(float x, float y)
{
    u64 r; asm("mov.b64 %0, {%1, %2};" : "=l"(r) : "f"(x), "f"(y)); return r;
}
__device__ __forceinline__ void unpack2(u64 v, float& x, float& y)
{
    asm("mov.b64 {%0, %1}, %2;" : "=f"(x), "=f"(y) : "l"(v));
}
__device__ __forceinline__ u64 ffma2(u64 a, u64 b, u64 c)
{
    u64 d; asm("fma.rn.f32x2 %0, %1, %2, %3;" : "=l"(d) : "l"(a), "l"(b), "l"(c)); return d;
}

// ---------------- node embedding ----------------
__global__ __launch_bounds__(128) void embed_kernel(
    const float* __restrict__ sf, const float* __restrict__ W1,
    const float* __restrict__ b1, const float* __restrict__ W2,
    const float* __restrict__ b2, const float* __restrict__ vf)
{
    __shared__ float ssf[8][S_IN];
    __shared__ float sh[8][HID];
    const int nb = blockIdx.x * 8;
    const int t  = threadIdx.x;

    for (int i = t; i < 8 * S_IN; i += 128) {
        int n = i / S_IN, k = i - n * S_IN;
        int node = nb + n;
        ssf[n][k] = (node < NN) ? sf[node * S_IN + k] : 0.f;
    }
    __syncthreads();

    float acc[8];
    float bb = b1[t];
#pragma unroll
    for (int n = 0; n < 8; n++) acc[n] = bb;
    for (int k = 0; k < S_IN; k++) {
        float w = W1[k * HID + t];
#pragma unroll
        for (int n = 0; n < 8; n++) acc[n] += ssf[n][k] * w;
    }
#pragma unroll
    for (int n = 0; n < 8; n++) sh[n][t] = fmaxf(acc[n], 0.f);
    __syncthreads();

    if (t < DD) {
        float acc2[8];
        float b2v = b2[t];
#pragma unroll
        for (int n = 0; n < 8; n++) acc2[n] = b2v;
        for (int k = 0; k < HID; k++) {
            float w = W2[k * DD + t];
#pragma unroll
            for (int n = 0; n < 8; n++) acc2[n] += sh[n][k] * w;
        }
#pragma unroll
        for (int n = 0; n < 8; n++)
            if (nb + n < NN) g_s[(nb + n) * DD + t] = acc2[n];
    }
    for (int i = t; i < 8 * VV * 3; i += 128) {
        int n = i / (VV * 3), k = i - n * (VV * 3);
        int node = nb + n;
        if (node < NN) g_v[node * VV * 3 + k] = vf[node * VV * 3 + k];
    }
}

__global__ void deg_kernel(const int* __restrict__ ei)
{
    int e = blockIdx.x * blockDim.x + threadIdx.x;
    if (e < NE) atomicAdd(&g_deg[ei[NE + e]], 1.0f);
}
__global__ void invdeg_kernel()
{
    int i = blockIdx.x * blockDim.x + threadIdx.x;
    if (i < NN) g_invdeg[i] = 1.0f / fmaxf(g_deg[i], 1.0f);
}

// ---------------- edge kernel: warp = 8 edges, f32x2 GEMV, batched gathers ----------------
#define EPW 8
#define XI_STR 100
#define SM_STR 68
#define G_STR  20
#define WARP_FLTS 1104
#define OFF_WSV  0                       // 48*64 = 3072
#define OFF_WGT  3072                    // 16*68 = 1088 (Wg^T, stride 68)
#define OFF_BG   4160                    // 16
#define OFF_WH16 4176                    // 16
#define OFF_WMUX 4192                    // 16
#define OFF_SRC  4208                    // 64 ints
#define OFF_DST  4272                    // 64 ints
#define OFF_SCR  4336                    // 16B aligned
#define SMEM_FLOATS (OFF_SCR + 8 * WARP_FLTS)
#define SMEM_BYTES  (SMEM_FLOATS * 4)

__global__ __launch_bounds__(256, 4) void edge_kernel(
    const float* __restrict__ ef, const float* __restrict__ xd,
    const float* __restrict__ dvec, const int* __restrict__ ei,
    const float* __restrict__ Wh, const float* __restrict__ WsV,
    const float* __restrict__ Wmu, const float* __restrict__ Wg,
    const float* __restrict__ bg, int compute_vm)
{
    extern __shared__ float smem[];
    float* sWsV  = smem + OFF_WSV;
    float* sWgT  = smem + OFF_WGT;
    float* sbg   = smem + OFF_BG;
    float* swh16 = smem + OFF_WH16;
    float* swmux = smem + OFF_WMUX;

    const int t = threadIdx.x;
    for (int i = t; i < 48 * 64; i += 256) sWsV[i] = WsV[i];
    for (int i = t; i < 16 * 64; i += 256) {
        int j = i >> 4, o = i & 15;            // Wg[j][o]
        sWgT[o * 68 + j] = Wg[i];
    }
    if (t < 16) {
        sbg[t]   = bg[t];
        swh16[t] = Wh[16 * HH + t];
        float a = 0.f;
#pragma unroll
        for (int h = 0; h < HH; h++) a += Wh[16 * HH + h] * Wmu[h * VV + t];
        swmux[t] = a;
    }
    __syncthreads();

    const int warp = t >> 5, lane = t & 31;
    float* scrXI = smem + OFF_SCR + warp * WARP_FLTS;
    float* scrSM = scrXI + 400;
    float* scrG  = scrXI + 944;
    int* ssrcw = (int*)(smem + OFF_SRC) + warp * EPW;
    int* sdstw = (int*)(smem + OFF_DST) + warp * EPW;

    const int hq  = lane >> 4;                  // half-warp id
    const int h16 = lane & 15;                  // h / o role
    const int q3  = lane >> 2, cg = lane & 3;   // gate roles
    const int qe  = lane >> 2;                  // ef role
    const int j0  = 2 * lane;

    const float inv_sigma = (float)NRBF / 10.0f;
    const float mu_step   = 10.0f / (float)(NRBF - 1);

    const int ntiles = NE / (8 * EPW);          // 12500 exact
    for (int tile = blockIdx.x; tile < ntiles; tile += gridDim.x) {
        const int ebase = tile * (8 * EPW) + warp * EPW;

        // ---- Phase 0: coalesced loads, stage src/dst ----
        if (lane < 8) {
            ssrcw[lane] = ei[ebase + lane];
            sdstw[lane] = ei[NE + ebase + lane];
        }
        float4 efv = *(const float4*)(ef + (size_t)ebase * 16 + lane * 4);
        float xdv = 0.f, dval = 0.f;
        if (lane < 24) xdv = xd[(size_t)ebase * 3 + lane];
        if (lane < 8)  dval = dvec[ebase + lane];
        __syncwarp();

        // ---- Batched gathers: all P + Vn loads issued up-front (MLP=12) ----
        float2 pe[EPW];
#pragma unroll
        for (int q = 0; q < EPW; q++)
            pe[q] = *(const float2*)&g_P[(size_t)ssrcw[q] * 64 + j0];
        float4 vnr[4];
#pragma unroll
        for (int p = 0; p < 4; p++)
            vnr[p] = *(const float4*)&g_Vn[(size_t)ssrcw[2 * p + hq] * 64 + h16 * 4];

        // ---- staging ef / rbf (independent of gathers; covers latency) ----
        {
            float* xip = scrXI + (qe & 3) * XI_STR;
            int jb = (16 + (lane & 3) * 4) * 2 + (qe >> 2);
            xip[jb]     = efv.x;
            xip[jb + 2] = efv.y;
            xip[jb + 4] = efv.z;
            xip[jb + 6] = efv.w;
        }
#pragma unroll
        for (int p = 0; p < 4; p++) {
            int q = 2 * p + hq;
            float de = __shfl_sync(0xffffffffu, dval, q);
            float tt = (de - (float)h16 * mu_step) * inv_sigma;
            scrXI[(q & 3) * XI_STR + h16 * 2 + (q >> 2)] = __expf(-tt * tt);
        }

        // ---- vnorm from vnr registers ----
#pragma unroll
        for (int p = 0; p < 4; p++) {
            int q = 2 * p + hq;
            float x0 = __shfl_sync(0xffffffffu, xdv, 3 * q);
            float x1 = __shfl_sync(0xffffffffu, xdv, 3 * q + 1);
            float x2 = __shfl_sync(0xffffffffu, xdv, 3 * q + 2);
            float dot = vnr[p].x * x0 + vnr[p].y * x1 + vnr[p].z * x2;
            float xsq = x0 * x0 + x1 * x1 + x2 * x2;
            float w = swh16[h16];
            scrXI[(q & 3) * XI_STR + (32 + h16) * 2 + (q >> 2)] =
                sqrtf(vnr[p].w + 2.f * w * dot + w * w * xsq + 1e-8f);
        }
        __syncwarp();

        // ---- Phase 3: sm = relu(P[src] + X @ WsV), f32x2 over edge pairs ----
        u64 acc0[4], acc1[4];
#pragma unroll
        for (int p = 0; p < 4; p++) {
            acc0[p] = pack2(pe[p].x, pe[p + 4].x);
            acc1[p] = pack2(pe[p].y, pe[p + 4].y);
        }
#pragma unroll
        for (int k = 0; k < 48; k += 2) {
            float2 w0 = *(const float2*)&sWsV[k * DD + j0];
            float2 w1 = *(const float2*)&sWsV[(k + 1) * DD + j0];
            u64 wx0 = pack2(w0.x, w0.x), wy0 = pack2(w0.y, w0.y);
            u64 wx1 = pack2(w1.x, w1.x), wy1 = pack2(w1.y, w1.y);
#pragma unroll
            for (int p = 0; p < 4; p++) {
                ulonglong2 xx = *(const ulonglong2*)(scrXI + p * XI_STR + k * 2);
                acc0[p] = ffma2(xx.x, wx0, acc0[p]);
                acc1[p] = ffma2(xx.x, wy0, acc1[p]);
                acc0[p] = ffma2(xx.y, wx1, acc0[p]);
                acc1[p] = ffma2(xx.y, wy1, acc1[p]);
            }
        }
#pragma unroll
        for (int p = 0; p < 4; p++) {
            float a, b, c, d;
            unpack2(acc0[p], a, b);
            unpack2(acc1[p], c, d);
            *(float2*)&scrSM[p * SM_STR + j0] =
                make_float2(fmaxf(a, 0.f), fmaxf(c, 0.f));
            *(float2*)&scrSM[(p + 4) * SM_STR + j0] =
                make_float2(fmaxf(b, 0.f), fmaxf(d, 0.f));
        }
        __syncwarp();

        // ---- scatter sm (v4) ----
#pragma unroll
        for (int q = 0; q < EPW; q++) {
            if (lane < 16) {
                float4 v = *(const float4*)&scrSM[q * SM_STR + lane * 4];
                red_add_v4(&g_aggs[(size_t)sdstw[q] * 64 + lane * 4],
                           v.x, v.y, v.z, v.w);
            }
        }

        if (compute_vm) {
            // ---- issue Mn gathers before gate (gate compute covers latency) ----
            float4 mnr[4];
#pragma unroll
            for (int p = 0; p < 4; p++)
                mnr[p] = *(const float4*)&g_Mn[(size_t)ssrcw[2 * p + hq] * 64 + h16 * 4];

            // ---- Phase 4: gate ----
            {
                const float* SM = scrSM + q3 * SM_STR;
                float a0 = sbg[cg], a1 = sbg[cg + 4], a2 = sbg[cg + 8], a3 = sbg[cg + 12];
#pragma unroll
                for (int j = 0; j < DD; j += 4) {
                    float4 s4 = *(const float4*)&SM[j];
                    float4 w0 = *(const float4*)&sWgT[cg * 68 + j];
                    float4 w1 = *(const float4*)&sWgT[(cg + 4) * 68 + j];
                    float4 w2 = *(const float4*)&sWgT[(cg + 8) * 68 + j];
                    float4 w3 = *(const float4*)&sWgT[(cg + 12) * 68 + j];
                    a0 += s4.x * w0.x + s4.y * w0.y + s4.z * w0.z + s4.w * w0.w;
                    a1 += s4.x * w1.x + s4.y * w1.y + s4.z * w1.z + s4.w * w1.w;
                    a2 += s4.x * w2.x + s4.y * w2.y + s4.z * w2.z + s4.w * w2.w;
                    a3 += s4.x * w3.x + s4.y * w3.y + s4.z * w3.z + s4.w * w3.w;
                }
                float* G = scrG + q3 * G_STR;
                G[cg]      = 1.f / (1.f + __expf(-a0));
                G[cg + 4]  = 1.f / (1.f + __expf(-a1));
                G[cg + 8]  = 1.f / (1.f + __expf(-a2));
                G[cg + 12] = 1.f / (1.f + __expf(-a3));
            }
            __syncwarp();

            // ---- Phase 5: vm = (Mn[src] + xd*wmux) * gate, direct red.v4 ----
#pragma unroll
            for (int p = 0; p < 4; p++) {
                int q = 2 * p + hq;
                int dq = sdstw[q];
                float x0 = __shfl_sync(0xffffffffu, xdv, 3 * q);
                float x1 = __shfl_sync(0xffffffffu, xdv, 3 * q + 1);
                float x2 = __shfl_sync(0xffffffffu, xdv, 3 * q + 2);
                float gt = scrG[q * G_STR + h16];
                float wm = swmux[h16];
                red_add_v4(&g_aggv[(size_t)dq * 64 + h16 * 4],
                           (mnr[p].x + x0 * wm) * gt,
                           (mnr[p].y + x1 * wm) * gt,
                           (mnr[p].z + x2 * wm) * gt, 0.f);
            }
        }
        __syncwarp();
    }
}

// ---------------- fused update + per-node precompute + agg zeroing ----------------
// mode: 0 = init (zero aggs/aggv, no residual), 1 = mid (update s,v; re-zero aggs/aggv),
//       2 = last (s only + out)
__global__ __launch_bounds__(256) void update_pre_kernel(
    const float* __restrict__ WsPnext, const float* __restrict__ bsnext,
    const float* __restrict__ Wh, const float* __restrict__ Wmu,
    float* __restrict__ out, int mode, int do_mn)
{
    __shared__ float sW[64 * 64];
    __shared__ float sS[32 * 65];
    __shared__ float sv[32 * 48];
    __shared__ float sVn[32 * 64];
    __shared__ float sWh[16 * 16];
    __shared__ float sWm[16 * 16];

    const int t = threadIdx.x;
    const int nb = blockIdx.x * 32;
    const int nl = t >> 3, j0 = (t & 7) * 8;
    const int node = nb + nl;
    const float4 zero4 = make_float4(0.f, 0.f, 0.f, 0.f);

    // ---- s path ----
    if (node < NN) {
        float4 s0 = *(const float4*)&g_s[(size_t)node * 64 + j0];
        float4 s1 = *(const float4*)&g_s[(size_t)node * 64 + j0 + 4];
        if (mode != 0) {
            float inv = g_invdeg[node];
            float4 a0 = *(const float4*)&g_aggs[(size_t)node * 64 + j0];
            float4 a1 = *(const float4*)&g_aggs[(size_t)node * 64 + j0 + 4];
            s0.x += a0.x * inv; s0.y += a0.y * inv; s0.z += a0.z * inv; s0.w += a0.w * inv;
            s1.x += a1.x * inv; s1.y += a1.y * inv; s1.z += a1.z * inv; s1.w += a1.w * inv;
            *(float4*)&g_s[(size_t)node * 64 + j0]     = s0;
            *(float4*)&g_s[(size_t)node * 64 + j0 + 4] = s1;
            if (mode == 2) {
                *(float4*)&out[(size_t)node * 64 + j0]     = s0;
                *(float4*)&out[(size_t)node * 64 + j0 + 4] = s1;
            }
        }
        // zero aggs for next layer (same addresses this thread just read)
        if (mode != 2) {
            *(float4*)&g_aggs[(size_t)node * 64 + j0]     = zero4;
            *(float4*)&g_aggs[(size_t)node * 64 + j0 + 4] = zero4;
        }
        sS[nl * 65 + j0]     = s0.x; sS[nl * 65 + j0 + 1] = s0.y;
        sS[nl * 65 + j0 + 2] = s0.z; sS[nl * 65 + j0 + 3] = s0.w;
        sS[nl * 65 + j0 + 4] = s1.x; sS[nl * 65 + j0 + 5] = s1.y;
        sS[nl * 65 + j0 + 6] = s1.z; sS[nl * 65 + j0 + 7] = s1.w;
    } else {
#pragma unroll
        for (int k = 0; k < 8; k++) sS[nl * 65 + j0 + k] = 0.f;
    }
    if (mode == 2) return;

    // ---- v path (reads aggv in mode 1) ----
    for (int i = t; i < 32 * 48; i += 256) {
        int n2 = i / 48, r = i - n2 * 48;
        int gn = nb + n2;
        float vv = 0.f;
        if (gn < NN) {
            vv = g_v[(size_t)gn * 48 + r];
            if (mode == 1) {
                int o = r / 3, d = r - 3 * o;
                vv += g_aggv[(size_t)gn * 64 + o * 4 + d] * g_invdeg[gn];
                g_v[(size_t)gn * 48 + r] = vv;
            }
        }
        sv[n2 * 48 + r] = vv;
    }

    for (int i = t * 4; i < 64 * 64; i += 1024)
        *(float4*)&sW[i] = *(const float4*)&WsPnext[i];
    if (t < 256) { sWh[t] = Wh[t]; sWm[t] = Wmu[t]; }
    __syncthreads();

    // ---- zero aggv for next layer (after all v-path reads completed) ----
    for (int i = t; i < 32 * 16; i += 256) {
        int n = i >> 4, c4 = i & 15;
        int gn = nb + n;
        if (gn < NN)
            *(float4*)&g_aggv[(size_t)gn * 64 + c4 * 4] = zero4;
    }

    // ---- P GEMM ----
    {
        float4 a0 = *(const float4*)(bsnext + j0);
        float4 a1 = *(const float4*)(bsnext + j0 + 4);
#pragma unroll 8
        for (int k = 0; k < 64; k++) {
            float a = sS[nl * 65 + k];
            float4 w0 = *(const float4*)&sW[k * 64 + j0];
            float4 w1 = *(const float4*)&sW[k * 64 + j0 + 4];
            a0.x += a * w0.x; a0.y += a * w0.y; a0.z += a * w0.z; a0.w += a * w0.w;
            a1.x += a * w1.x; a1.y += a * w1.y; a1.z += a * w1.z; a1.w += a * w1.w;
        }
        if (node < NN) {
            *(float4*)&g_P[(size_t)node * 64 + j0]     = a0;
            *(float4*)&g_P[(size_t)node * 64 + j0 + 4] = a1;
        }
    }

    // ---- Vn = v @ Wh[0:16] ----
    for (int i = t; i < 32 * 48; i += 256) {
        int n = i / 48, r = i - n * 48;
        int h = r / 3, d = r - 3 * h;
        float a = 0.f;
#pragma unroll
        for (int c = 0; c < 16; c++) a += sv[n * 48 + c * 3 + d] * sWh[c * 16 + h];
        sVn[n * 64 + h * 4 + d] = a;
    }
    __syncthreads();

    // ---- nsq + write g_Vn ----
    for (int i = t; i < 32 * 16; i += 256) {
        int n = i >> 4, h = i & 15;
        int gn = nb + n;
        if (gn < NN) {
            float a = sVn[n * 64 + h * 4];
            float b = sVn[n * 64 + h * 4 + 1];
            float c = sVn[n * 64 + h * 4 + 2];
            *(float4*)&g_Vn[(size_t)gn * 64 + h * 4] =
                make_float4(a, b, c, a * a + b * b + c * c);
        }
    }

    // ---- Mn = Vn @ Wmu ----
    if (do_mn) {
        for (int i = t; i < 32 * 48; i += 256) {
            int n = i / 48, r = i - n * 48;
            int o = r / 3, d = r - 3 * o;
            int gn = nb + n;
            if (gn < NN) {
                float a = 0.f;
#pragma unroll
                for (int h = 0; h < 16; h++) a += sVn[n * 64 + h * 4 + d] * sWm[h * 16 + o];
                g_Mn[(size_t)gn * 64 + o * 4 + d] = a;
            }
        }
    }
}

extern "C" void kernel_launch(void* const* d_in, const int* in_sizes, int n_in,
                              void* d_out, int out_size)
{
    const float* sf  = (const float*)d_in[0];
    const float* vf  = (const float*)d_in[2];
    const float* ef  = (const float*)d_in[3];
    const float* xd  = (const float*)d_in[4];
    const float* dv  = (const float*)d_in[5];
    const int*   eix = (const int*)  d_in[6];
    const float* W1  = (const float*)d_in[7];
    const float* b1  = (const float*)d_in[8];
    const float* W2  = (const float*)d_in[9];
    const float* b2  = (const float*)d_in[10];
    const float* Wh  = (const float*)d_in[11];
    const float* Ws  = (const float*)d_in[12];
    const float* bs  = (const float*)d_in[13];
    const float* Wmu = (const float*)d_in[14];
    const float* Wg  = (const float*)d_in[15];
    const float* bg  = (const float*)d_in[16];
    (void)in_sizes; (void)n_in; (void)out_size;

    cudaFuncSetAttribute(edge_kernel,
                         cudaFuncAttributeMaxDynamicSharedMemorySize, SMEM_BYTES);

    void *p_deg = nullptr;
    cudaGetSymbolAddress(&p_deg, g_deg);

    embed_kernel<<<(NN + 7) / 8, 128>>>(sf, W1, b1, W2, b2, vf);
    cudaMemsetAsync(p_deg, 0, NN * sizeof(float));
    deg_kernel<<<(NE + 255) / 256, 256>>>(eix);
    invdeg_kernel<<<(NN + 255) / 256, 256>>>();

    const int nblk = (NN + 31) / 32;
    // init: P0, Vn0, Mn0 + zero aggs/aggv
    update_pre_kernel<<<nblk, 256>>>(Ws, bs, Wh, Wmu, nullptr, 0, 1);

    for (int l = 0; l < NLAYER; l++) {
        int vm = (l < NLAYER - 1);
        edge_kernel<<<1184, 256, SMEM_BYTES>>>(
            ef, xd, dv, eix,
            Wh  + l * VCIN * HH,
            Ws  + (size_t)l * 112 * 64 + 64 * 64,
            Wmu + l * HH * VV,
            Wg  + l * DD * VV,
            bg  + l * VV, vm);
        if (l < NLAYER - 1) {
            int ln = l + 1;
            update_pre_kernel<<<nblk, 256>>>(
                Ws + (size_t)ln * 112 * 64, bs + ln * DD,
                Wh + ln * VCIN * HH, Wmu + ln * HH * VV,
                nullptr, 1, (ln < NLAYER - 1) ? 1 : 0);
        } else {
            update_pre_kernel<<<nblk, 256>>>(
                Ws, bs, Wh, Wmu, (float*)d_out, 2, 0);
        }
    }
}